// round 9
// baseline (speedup 1.0000x reference)
#include <cuda_runtime.h>
#include <math.h>

#define N_NODES 8192
#define SEQ 256
#define H 32
#define NPB 8
#define NE 262144

typedef unsigned long long ull;

__device__ float g_h2[N_NODES * H];
__device__ float g_hW[N_NODES * H];
__device__ float g_agg[N_NODES * H];
__device__ float g_dinv[N_NODES];

__device__ __forceinline__ void ffma2(ull& d, ull a, ull b) {
    asm("fma.rn.f32x2 %0, %1, %2, %0;" : "+l"(d) : "l"(a), "l"(b));
}
__device__ __forceinline__ void fadd2(ull& d, ull a) {
    asm("add.rn.f32x2 %0, %0, %1;" : "+l"(d) : "l"(a));
}
__device__ __forceinline__ ull pack2(float lo, float hi) {
    ull r; asm("mov.b64 %0, {%1, %2};" : "=l"(r) : "f"(lo), "f"(hi)); return r;
}
__device__ __forceinline__ float2 unpack2(ull v) {
    float2 r; asm("mov.b64 {%0, %1}, %2;" : "=f"(r.x), "=f"(r.y) : "l"(v)); return r;
}
__device__ __forceinline__ float tanhap(float x) {
    float r; asm("tanh.approx.f32 %0, %1;" : "=f"(r) : "f"(x)); return r;
}
__device__ __forceinline__ float sigap(float x) {
    return fmaf(0.5f, tanhap(0.5f * x), 0.5f);
}

// =====================================================================
// Fused 2-layer LSTM with LN folded into the LSTM2 matvec.
// Virtual k-space: z1 = Whh1*h1 (k 0-31), u2 = Wtil*h1 (k 32-63),
// u3 = Whh2*h2 (k 64-95).  Each warp owns a 24-k window:
//   w0: z1[0:24)   w1: z1[24:32)+u2[0:16)  w2: u2[16:32)+u3[0:8)  w3: u3[8:32)
// Partial sums to padded zp arrays (2 slots); phase2 assembles, activates,
// updates cells + LN stats.  2 barriers/step.
// =====================================================================
__global__ void __launch_bounds__(128, 3) lstm_kernel(
    const float* __restrict__ x,
    const float* __restrict__ Wih1, const float* __restrict__ Whh1,
    const float* __restrict__ bih1, const float* __restrict__ bhh1,
    const float* __restrict__ ln_g, const float* __restrict__ ln_b,
    const float* __restrict__ Wih2, const float* __restrict__ Whh2,
    const float* __restrict__ bih2, const float* __restrict__ bhh2)
{
    __shared__ __align__(16) float xs[NPB][SEQ];
    __shared__ __align__(16) float h1s[NPB][H];
    __shared__ __align__(16) float h2s[NPB][H];
    __shared__ float zp1[NPB][128][3];
    __shared__ float zp2[NPB][128][3];
    __shared__ float zp3[NPB][128][3];
    __shared__ float stil_s[128], q_s[128];

    const int tid  = threadIdx.x;
    const int wid  = tid >> 5;
    const int lane = tid & 31;
    const int base = blockIdx.x * NPB;

    // ---- row constants: s~ and q (thread tid owns row tid) ----
    {
        float st = 0.f, qq = 0.f;
        for (int k = 0; k < H; k++) {
            float w = Wih2[tid * H + k];
            st = fmaf(w, ln_g[k], st);
            qq = fmaf(w, ln_b[k], qq);
        }
        stil_s[tid] = st;
        q_s[tid]    = qq + bih2[tid] + bhh2[tid];
    }

    // ---- per-warp chunk geometry ----
    int kb0, kb1, kb2, mt0, mt1, mt2;      // mat: 1=Whh1 2=Wtil 3=Whh2
    const float* sbase1 = &h1s[0][0];
    const float* sbase2 = &h2s[0][0];
    const float *sp0, *sp1, *sp2;
    float *stA, *stB = 0;
    switch (wid) {
    case 0: kb0=0;  kb1=8;  kb2=16; mt0=1; mt1=1; mt2=1;
            sp0=sbase1+kb0; sp1=sbase1+kb1; sp2=sbase1+kb2;
            stA=&zp1[0][0][0]; break;
    case 1: kb0=24; kb1=0;  kb2=8;  mt0=1; mt1=2; mt2=2;
            sp0=sbase1+kb0; sp1=sbase1+kb1; sp2=sbase1+kb2;
            stA=&zp1[0][0][1]; stB=&zp2[0][0][0]; break;
    case 2: kb0=16; kb1=24; kb2=0;  mt0=2; mt1=2; mt2=3;
            sp0=sbase1+kb0; sp1=sbase1+kb1; sp2=sbase2+kb2;
            stA=&zp2[0][0][1]; stB=&zp3[0][0][0]; break;
    default:kb0=8;  kb1=16; kb2=24; mt0=3; mt1=3; mt2=3;
            sp0=sbase2+kb0; sp1=sbase2+kb1; sp2=sbase2+kb2;
            stA=&zp3[0][0][1]; break;
    }
    const bool hasB = (wid == 1) || (wid == 2);

    // ---- weights: 3 chunks x 4 rows x 4 pairs ----
    ull wreg[3][4][4];
    {
        int kbs[3] = {kb0, kb1, kb2};
        int mts[3] = {mt0, mt1, mt2};
        for (int c = 0; c < 3; c++)
            for (int g = 0; g < 4; g++) {
                int r = 32 * g + lane;
                for (int p = 0; p < 4; p++) {
                    int k = kbs[c] + 2 * p;
                    float a, b;
                    if (mts[c] == 1)      { a = Whh1[r*H+k];            b = Whh1[r*H+k+1]; }
                    else if (mts[c] == 2) { a = Wih2[r*H+k]*ln_g[k];    b = Wih2[r*H+k+1]*ln_g[k+1]; }
                    else                  { a = Whh2[r*H+k];            b = Whh2[r*H+k+1]; }
                    wreg[c][g][p] = pack2(a, b);
                }
            }
    }
    float wx[4], bb[4];
#pragma unroll
    for (int g = 0; g < 4; g++) {
        int r = 32 * g + lane;
        wx[g] = Wih1[r];
        bb[g] = bih1[r] + bhh1[r];
    }

    // stage x, zero states
    for (int idx = tid; idx < NPB * SEQ; idx += 128) {
        int m = idx >> 8, t = idx & 255;
        xs[m][t] = x[(base + m) * SEQ + t];
    }
    {
        int m = tid >> 5;
        h1s[m][lane] = 0.f; h1s[m + 4][lane] = 0.f;
        h2s[m][lane] = 0.f; h2s[m + 4][lane] = 0.f;
    }
    __syncthreads();

    float stil_r[4], q_r[4];
#pragma unroll
    for (int g = 0; g < 4; g++) { stil_r[g] = stil_s[32*g+lane]; q_r[g] = q_s[32*g+lane]; }

    const int nA = wid, nB = wid + 4;       // phase2-owned nodes
    float c1a = 0.f, c1b = 0.f, c2a = 0.f, c2b = 0.f;
    float rinvA = 0.f, rinvB = 0.f, mriA = 0.f, mriB = 0.f;
    const float* zp1f = &zp1[0][0][0];
    const float* zp2f = &zp2[0][0][0];
    const float* zp3f = &zp3[0][0][0];

    for (int t = 0; t <= SEQ; t++) {
        const int tx = (t < SEQ) ? t : SEQ - 1;
        // ================= phase1: partial matvecs =================
#pragma unroll
        for (int m = 0; m < NPB; m++) {
            ull accA[4], accB[4];
            float xt = (wid == 0) ? xs[m][tx] : 0.f;
#pragma unroll
            for (int g = 0; g < 4; g++) {
                accA[g] = pack2((wid == 0) ? fmaf(xt, wx[g], bb[g]) : 0.f, 0.f);
                accB[g] = pack2(0.f, 0.f);
            }
            {   // chunk 0 -> always A
                ulonglong2 v0 = *(const ulonglong2*)(sp0 + m * H);
                ulonglong2 v1 = *(const ulonglong2*)(sp0 + m * H + 4);
#pragma unroll
                for (int g = 0; g < 4; g++) {
                    ffma2(accA[g], wreg[0][g][0], v0.x); ffma2(accA[g], wreg[0][g][1], v0.y);
                    ffma2(accA[g], wreg[0][g][2], v1.x); ffma2(accA[g], wreg[0][g][3], v1.y);
                }
            }
            {   // chunk 1 -> B iff wid==1
                ulonglong2 v0 = *(const ulonglong2*)(sp1 + m * H);
                ulonglong2 v1 = *(const ulonglong2*)(sp1 + m * H + 4);
                if (wid == 1) {
#pragma unroll
                    for (int g = 0; g < 4; g++) {
                        ffma2(accB[g], wreg[1][g][0], v0.x); ffma2(accB[g], wreg[1][g][1], v0.y);
                        ffma2(accB[g], wreg[1][g][2], v1.x); ffma2(accB[g], wreg[1][g][3], v1.y);
                    }
                } else {
#pragma unroll
                    for (int g = 0; g < 4; g++) {
                        ffma2(accA[g], wreg[1][g][0], v0.x); ffma2(accA[g], wreg[1][g][1], v0.y);
                        ffma2(accA[g], wreg[1][g][2], v1.x); ffma2(accA[g], wreg[1][g][3], v1.y);
                    }
                }
            }
            {   // chunk 2 -> B iff wid in {1,2}
                ulonglong2 v0 = *(const ulonglong2*)(sp2 + m * H);
                ulonglong2 v1 = *(const ulonglong2*)(sp2 + m * H + 4);
                if (hasB) {
#pragma unroll
                    for (int g = 0; g < 4; g++) {
                        ffma2(accB[g], wreg[2][g][0], v0.x); ffma2(accB[g], wreg[2][g][1], v0.y);
                        ffma2(accB[g], wreg[2][g][2], v1.x); ffma2(accB[g], wreg[2][g][3], v1.y);
                    }
                } else {
#pragma unroll
                    for (int g = 0; g < 4; g++) {
                        ffma2(accA[g], wreg[2][g][0], v0.x); ffma2(accA[g], wreg[2][g][1], v0.y);
                        ffma2(accA[g], wreg[2][g][2], v1.x); ffma2(accA[g], wreg[2][g][3], v1.y);
                    }
                }
            }
#pragma unroll
            for (int g = 0; g < 4; g++) {
                int off = (m * 128 + 32 * g + lane) * 3;
                float2 pa = unpack2(accA[g]);
                stA[off] = pa.x + pa.y;
                if (hasB) { float2 pb = unpack2(accB[g]); stB[off] = pb.x + pb.y; }
            }
        }
        __syncthreads();

        // ================= phase2 =================
        if (t) {   // cell2 for state (t-1)
            float gA[4], gB[4];
#pragma unroll
            for (int g = 0; g < 4; g++) {
                int oA = (nA * 128 + 32 * g + lane) * 3;
                int oB = (nB * 128 + 32 * g + lane) * 3;
                float zA = fmaf(rinvA, zp2f[oA] + zp2f[oA+1],
                                fmaf(mriA, stil_r[g], q_r[g]) + zp3f[oA] + zp3f[oA+1]);
                float zB = fmaf(rinvB, zp2f[oB] + zp2f[oB+1],
                                fmaf(mriB, stil_r[g], q_r[g]) + zp3f[oB] + zp3f[oB+1]);
                gA[g] = (g == 2) ? tanhap(zA) : sigap(zA);
                gB[g] = (g == 2) ? tanhap(zB) : sigap(zB);
            }
            c2a = fmaf(gA[1], c2a, gA[0] * gA[2]);
            c2b = fmaf(gB[1], c2b, gB[0] * gB[2]);
            float hA = gA[3] * tanhap(c2a);
            float hB = gB[3] * tanhap(c2b);
            if (t < SEQ) { h2s[nA][lane] = hA; h2s[nB][lane] = hB; }
            else {
                g_h2[(base + nA) * H + lane] = hA;
                g_h2[(base + nB) * H + lane] = hB;
            }
        }
        if (t < SEQ) {   // cell1(t) + LN stats
            float gA[4], gB[4];
#pragma unroll
            for (int g = 0; g < 4; g++) {
                int oA = (nA * 128 + 32 * g + lane) * 3;
                int oB = (nB * 128 + 32 * g + lane) * 3;
                float zA = zp1f[oA] + zp1f[oA+1];
                float zB = zp1f[oB] + zp1f[oB+1];
                gA[g] = (g == 2) ? tanhap(zA) : sigap(zA);
                gB[g] = (g == 2) ? tanhap(zB) : sigap(zB);
            }
            c1a = fmaf(gA[1], c1a, gA[0] * gA[2]);
            c1b = fmaf(gB[1], c1b, gB[0] * gB[2]);
            float hA = gA[3] * tanhap(c1a);
            float hB = gB[3] * tanhap(c1b);

            ull svA = pack2(hA, hA * hA);
            ull svB = pack2(hB, hB * hB);
#pragma unroll
            for (int off = 16; off; off >>= 1) {
                fadd2(svA, __shfl_xor_sync(0xffffffffu, svA, off));
                fadd2(svB, __shfl_xor_sync(0xffffffffu, svB, off));
            }
            float2 sA = unpack2(svA), sB = unpack2(svB);
            float muA  = sA.x * (1.0f / H);
            float muB  = sB.x * (1.0f / H);
            rinvA = rsqrtf(fmaf(-muA, muA, sA.y * (1.0f / H)) + 1e-5f);
            rinvB = rsqrtf(fmaf(-muB, muB, sB.y * (1.0f / H)) + 1e-5f);
            mriA = -muA * rinvA;
            mriB = -muB * rinvB;
            h1s[nA][lane] = hA;
            h1s[nB][lane] = hB;
        }
        __syncthreads();
    }
}

// =====================================================================
// GCN stage (unchanged)
// =====================================================================
__global__ void dinv_init_kernel() {
    int i = blockIdx.x * blockDim.x + threadIdx.x;
    if (i < N_NODES) g_dinv[i] = 1.0f;
}
__global__ void deg_acc_kernel(const int* __restrict__ ei, const float* __restrict__ ew) {
    int e = blockIdx.x * blockDim.x + threadIdx.x;
    if (e < NE) atomicAdd(&g_dinv[ei[NE + e]], ew[e]);
}
__global__ void dinv_fin_kernel() {
    int i = blockIdx.x * blockDim.x + threadIdx.x;
    if (i < N_NODES) g_dinv[i] = rsqrtf(g_dinv[i]);
}

__global__ void gcn_pre_kernel(const float* __restrict__ inp, const float* __restrict__ Wg,
                               const float* __restrict__ bprev, int apply_elu)
{
    __shared__ float Ws[H * H];
    __shared__ float rows[8][H];
    int tid = threadIdx.x;
    int m = tid >> 5, u = tid & 31;
    int n = blockIdx.x * 8 + m;
    for (int i = tid; i < H * H; i += 256) Ws[i] = Wg[i];
    float v = inp[n * H + u];
    if (apply_elu) { v += bprev[u]; v = v > 0.f ? v : expm1f(v); }
    rows[m][u] = v;
    __syncthreads();
    float acc = 0.f;
#pragma unroll
    for (int k = 0; k < H; k++) acc = fmaf(rows[m][k], Ws[k * H + u], acc);
    float di = g_dinv[n];
    g_hW[n * H + u]  = acc;
    g_agg[n * H + u] = acc * di * di;
}

__global__ void gcn_scatter_kernel(const int* __restrict__ ei, const float* __restrict__ ew)
{
    int idx = blockIdx.x * blockDim.x + threadIdx.x;
    int e = idx >> 5, u = idx & 31;
    int s = ei[e];
    int d = ei[NE + e];
    float nrm = g_dinv[s] * ew[e] * g_dinv[d];
    atomicAdd(&g_agg[d * H + u], nrm * g_hW[s * H + u]);
}

__global__ void final_kernel(const float* __restrict__ bg2, const float* __restrict__ Wfc,
                             const float* __restrict__ bfc, float* __restrict__ out)
{
    int tid = threadIdx.x;
    int m = tid >> 5, u = tid & 31;
    int n = blockIdx.x * 8 + m;
    float g = g_agg[n * H + u] + bg2[u];
    g = g > 0.f ? g : expm1f(g);
    float s = g;
#pragma unroll
    for (int off = 16; off; off >>= 1) s += __shfl_xor_sync(0xffffffffu, s, off);
    float mean = s * (1.0f / H);
    float h2u = g_h2[n * H + u];
    float p0 = h2u * Wfc[u];
    float p1 = h2u * Wfc[33 + u];
#pragma unroll
    for (int off = 16; off; off >>= 1) {
        p0 += __shfl_xor_sync(0xffffffffu, p0, off);
        p1 += __shfl_xor_sync(0xffffffffu, p1, off);
    }
    if (u == 0) {
        float o0 = p0 + mean * Wfc[32]      + bfc[0];
        float o1 = p1 + mean * Wfc[33 + 32] + bfc[1];
        float mx = fmaxf(o0, o1);
        float lse = mx + logf(expf(o0 - mx) + expf(o1 - mx));
        out[n * 2 + 0] = o0 - lse;
        out[n * 2 + 1] = o1 - lse;
    }
}

// =====================================================================
extern "C" void kernel_launch(void* const* d_in, const int* in_sizes, int n_in,
                              void* d_out, int out_size)
{
    const float* x    = (const float*)d_in[0];
    const float* ew   = (const float*)d_in[1];
    const float* Wih1 = (const float*)d_in[2];
    const float* Whh1 = (const float*)d_in[3];
    const float* bih1 = (const float*)d_in[4];
    const float* bhh1 = (const float*)d_in[5];
    const float* lng  = (const float*)d_in[6];
    const float* lnb  = (const float*)d_in[7];
    const float* Wih2 = (const float*)d_in[8];
    const float* Whh2 = (const float*)d_in[9];
    const float* bih2 = (const float*)d_in[10];
    const float* bhh2 = (const float*)d_in[11];
    const float* Wg1  = (const float*)d_in[12];
    const float* bg1  = (const float*)d_in[13];
    const float* Wg2  = (const float*)d_in[14];
    const float* bg2  = (const float*)d_in[15];
    const float* Wfc  = (const float*)d_in[16];
    const float* bfc  = (const float*)d_in[17];
    const int*   eidx = (const int*)d_in[18];
    float* out = (float*)d_out;

    // keep lstm_kernel as launch #4 for the fixed-skip ncu capture
    dinv_init_kernel<<<N_NODES / 256, 256>>>();
    deg_acc_kernel<<<NE / 256, 256>>>(eidx, ew);
    dinv_fin_kernel<<<N_NODES / 256, 256>>>();

    lstm_kernel<<<N_NODES / NPB, 128>>>(x, Wih1, Whh1, bih1, bhh1, lng, lnb,
                                        Wih2, Whh2, bih2, bhh2);

    gcn_pre_kernel<<<N_NODES / 8, 256>>>(g_h2, Wg1, bg1, 0);
    gcn_scatter_kernel<<<(NE * 32) / 256, 256>>>(eidx, ew);

    gcn_pre_kernel<<<N_NODES / 8, 256>>>(g_agg, Wg2, bg1, 1);
    gcn_scatter_kernel<<<(NE * 32) / 256, 256>>>(eidx, ew);

    final_kernel<<<N_NODES / 8, 256>>>(bg2, Wfc, bfc, out);
}

// round 10
// speedup vs baseline: 1.0231x; 1.0231x over previous
#include <cuda_runtime.h>
#include <math.h>

#define N_NODES 8192
#define SEQ 256
#define H 32
#define NPB 8
#define NE 262144

typedef unsigned long long ull;

__device__ float g_h2[N_NODES * H];
__device__ float g_hW[N_NODES * H];
__device__ float g_agg[N_NODES * H];
__device__ float g_dinv[N_NODES];

__device__ __forceinline__ void ffma2(ull& d, ull a, ull b) {
    asm("fma.rn.f32x2 %0, %1, %2, %0;" : "+l"(d) : "l"(a), "l"(b));
}
__device__ __forceinline__ void fadd2(ull& d, ull a) {
    asm("add.rn.f32x2 %0, %0, %1;" : "+l"(d) : "l"(a));
}
__device__ __forceinline__ ull pack2(float lo, float hi) {
    ull r; asm("mov.b64 %0, {%1, %2};" : "=l"(r) : "f"(lo), "f"(hi)); return r;
}
__device__ __forceinline__ float2 unpack2(ull v) {
    float2 r; asm("mov.b64 {%0, %1}, %2;" : "=f"(r.x), "=f"(r.y) : "l"(v)); return r;
}
__device__ __forceinline__ float tanhap(float x) {
    float r; asm("tanh.approx.f32 %0, %1;" : "=f"(r) : "f"(x)); return r;
}
__device__ __forceinline__ float sigap(float x) {
    return fmaf(0.5f, tanhap(0.5f * x), 0.5f);
}

// =====================================================================
// Fused 2-layer LSTM, LN folded into LSTM2 matvec (Wtil = Wih2*diag(g)).
// Virtual k-space 96 wide, each warp owns 24 k; partials to slot-major
// zp[6][NPB][128]: {z1a,z1b,u2a,u2b,u3a,u3b}. 4 blocks/SM target.
// =====================================================================
__global__ void __launch_bounds__(128, 4) lstm_kernel(
    const float* __restrict__ x,
    const float* __restrict__ Wih1, const float* __restrict__ Whh1,
    const float* __restrict__ bih1, const float* __restrict__ bhh1,
    const float* __restrict__ ln_g, const float* __restrict__ ln_b,
    const float* __restrict__ Wih2, const float* __restrict__ Whh2,
    const float* __restrict__ bih2, const float* __restrict__ bhh2)
{
    __shared__ __align__(16) float xs[NPB][SEQ];
    __shared__ __align__(16) float h1s[NPB][H];
    __shared__ __align__(16) float h2s[NPB][H];
    __shared__ float zp[6][NPB][128];
    __shared__ float2 stq[128];     // (stil, q)
    __shared__ float2 wxb[128];     // (Wih1 row, bias1 row)

    const int tid  = threadIdx.x;
    const int wid  = tid >> 5;
    const int lane = tid & 31;
    const int base = blockIdx.x * NPB;

    // row constants (thread tid owns row tid)
    {
        float st = 0.f, qq = 0.f;
        for (int k = 0; k < H; k++) {
            float w = Wih2[tid * H + k];
            st = fmaf(w, ln_g[k], st);
            qq = fmaf(w, ln_b[k], qq);
        }
        stq[tid] = make_float2(st, qq + bih2[tid] + bhh2[tid]);
        wxb[tid] = make_float2(Wih1[tid], bih1[tid] + bhh1[tid]);
    }

    // per-warp chunk geometry (3 chunks of 8 k each)
    int kb0, kb1, kb2, mt0, mt1, mt2;      // mat: 1=Whh1 2=Wtil 3=Whh2
    const float *sp0, *sp1, *sp2;
    float *stA, *stB = &zp[2][0][0];
    switch (wid) {
    case 0: kb0=0;  kb1=8;  kb2=16; mt0=1; mt1=1; mt2=1;
            sp0=&h1s[0][kb0]; sp1=&h1s[0][kb1]; sp2=&h1s[0][kb2];
            stA=&zp[0][0][0]; break;
    case 1: kb0=24; kb1=0;  kb2=8;  mt0=1; mt1=2; mt2=2;
            sp0=&h1s[0][kb0]; sp1=&h1s[0][kb1]; sp2=&h1s[0][kb2];
            stA=&zp[1][0][0]; stB=&zp[2][0][0]; break;
    case 2: kb0=16; kb1=24; kb2=0;  mt0=2; mt1=2; mt2=3;
            sp0=&h1s[0][kb0]; sp1=&h1s[0][kb1]; sp2=&h2s[0][kb2];
            stA=&zp[3][0][0]; stB=&zp[4][0][0]; break;
    default:kb0=8;  kb1=16; kb2=24; mt0=3; mt1=3; mt2=3;
            sp0=&h2s[0][kb0]; sp1=&h2s[0][kb1]; sp2=&h2s[0][kb2];
            stA=&zp[5][0][0]; break;
    }
    const bool hasB = (wid == 1) || (wid == 2);

    // weights: 3 chunks x 4 gate-rows x 4 pairs
    ull wreg[3][4][4];
    {
        int kbs[3] = {kb0, kb1, kb2};
        int mts[3] = {mt0, mt1, mt2};
        for (int c = 0; c < 3; c++)
            for (int g = 0; g < 4; g++) {
                int r = 32 * g + lane;
                for (int p = 0; p < 4; p++) {
                    int k = kbs[c] + 2 * p;
                    float a, b;
                    if (mts[c] == 1)      { a = Whh1[r*H+k];         b = Whh1[r*H+k+1]; }
                    else if (mts[c] == 2) { a = Wih2[r*H+k]*ln_g[k]; b = Wih2[r*H+k+1]*ln_g[k+1]; }
                    else                  { a = Whh2[r*H+k];         b = Whh2[r*H+k+1]; }
                    wreg[c][g][p] = pack2(a, b);
                }
            }
    }

    for (int idx = tid; idx < NPB * SEQ; idx += 128) {
        int m = idx >> 8, t = idx & 255;
        xs[m][t] = x[(base + m) * SEQ + t];
    }
    {
        int m = tid >> 5;
        h1s[m][lane] = 0.f; h1s[m + 4][lane] = 0.f;
        h2s[m][lane] = 0.f; h2s[m + 4][lane] = 0.f;
    }
    __syncthreads();

    const int nA = wid, nB = wid + 4;
    float c1a = 0.f, c1b = 0.f, c2a = 0.f, c2b = 0.f;
    float rinvA = 0.f, rinvB = 0.f, mriA = 0.f, mriB = 0.f;

    for (int t = 0; t <= SEQ; t++) {
        // ================= phase1: partial matvecs =================
#pragma unroll
        for (int m = 0; m < NPB; m++) {
            ull accA[4], accB[4];
#pragma unroll
            for (int g = 0; g < 4; g++) { accA[g] = 0ULL; accB[g] = 0ULL; }
            {
                ulonglong2 v0 = *(const ulonglong2*)(sp0 + m * H);
                ulonglong2 v1 = *(const ulonglong2*)(sp0 + m * H + 4);
#pragma unroll
                for (int g = 0; g < 4; g++) {
                    ffma2(accA[g], wreg[0][g][0], v0.x); ffma2(accA[g], wreg[0][g][1], v0.y);
                    ffma2(accA[g], wreg[0][g][2], v1.x); ffma2(accA[g], wreg[0][g][3], v1.y);
                }
            }
            {
                ulonglong2 v0 = *(const ulonglong2*)(sp1 + m * H);
                ulonglong2 v1 = *(const ulonglong2*)(sp1 + m * H + 4);
                if (wid == 1) {
#pragma unroll
                    for (int g = 0; g < 4; g++) {
                        ffma2(accB[g], wreg[1][g][0], v0.x); ffma2(accB[g], wreg[1][g][1], v0.y);
                        ffma2(accB[g], wreg[1][g][2], v1.x); ffma2(accB[g], wreg[1][g][3], v1.y);
                    }
                } else {
#pragma unroll
                    for (int g = 0; g < 4; g++) {
                        ffma2(accA[g], wreg[1][g][0], v0.x); ffma2(accA[g], wreg[1][g][1], v0.y);
                        ffma2(accA[g], wreg[1][g][2], v1.x); ffma2(accA[g], wreg[1][g][3], v1.y);
                    }
                }
            }
            {
                ulonglong2 v0 = *(const ulonglong2*)(sp2 + m * H);
                ulonglong2 v1 = *(const ulonglong2*)(sp2 + m * H + 4);
                if (hasB) {
#pragma unroll
                    for (int g = 0; g < 4; g++) {
                        ffma2(accB[g], wreg[2][g][0], v0.x); ffma2(accB[g], wreg[2][g][1], v0.y);
                        ffma2(accB[g], wreg[2][g][2], v1.x); ffma2(accB[g], wreg[2][g][3], v1.y);
                    }
                } else {
#pragma unroll
                    for (int g = 0; g < 4; g++) {
                        ffma2(accA[g], wreg[2][g][0], v0.x); ffma2(accA[g], wreg[2][g][1], v0.y);
                        ffma2(accA[g], wreg[2][g][2], v1.x); ffma2(accA[g], wreg[2][g][3], v1.y);
                    }
                }
            }
#pragma unroll
            for (int g = 0; g < 4; g++) {
                int off = m * 128 + 32 * g + lane;
                float2 pa = unpack2(accA[g]);
                stA[off] = pa.x + pa.y;
                if (hasB) { float2 pb = unpack2(accB[g]); stB[off] = pb.x + pb.y; }
            }
        }
        __syncthreads();

        // ================= phase2 =================
        if (t) {   // cell2 for step (t-1)
            float gA[4], gB[4];
#pragma unroll
            for (int g = 0; g < 4; g++) {
                int r = 32 * g + lane;
                float2 st = stq[r];
                float zA = fmaf(rinvA, zp[2][nA][r] + zp[3][nA][r],
                                fmaf(mriA, st.x, st.y) + zp[4][nA][r] + zp[5][nA][r]);
                float zB = fmaf(rinvB, zp[2][nB][r] + zp[3][nB][r],
                                fmaf(mriB, st.x, st.y) + zp[4][nB][r] + zp[5][nB][r]);
                gA[g] = (g == 2) ? tanhap(zA) : sigap(zA);
                gB[g] = (g == 2) ? tanhap(zB) : sigap(zB);
            }
            c2a = fmaf(gA[1], c2a, gA[0] * gA[2]);
            c2b = fmaf(gB[1], c2b, gB[0] * gB[2]);
            float hA = gA[3] * tanhap(c2a);
            float hB = gB[3] * tanhap(c2b);
            if (t < SEQ) { h2s[nA][lane] = hA; h2s[nB][lane] = hB; }
            else {
                g_h2[(base + nA) * H + lane] = hA;
                g_h2[(base + nB) * H + lane] = hB;
            }
        }
        if (t < SEQ) {   // cell1(t) + LN stats
            float xtA = xs[nA][t], xtB = xs[nB][t];
            float gA[4], gB[4];
#pragma unroll
            for (int g = 0; g < 4; g++) {
                int r = 32 * g + lane;
                float2 wb = wxb[r];
                float zA = zp[0][nA][r] + zp[1][nA][r] + fmaf(xtA, wb.x, wb.y);
                float zB = zp[0][nB][r] + zp[1][nB][r] + fmaf(xtB, wb.x, wb.y);
                gA[g] = (g == 2) ? tanhap(zA) : sigap(zA);
                gB[g] = (g == 2) ? tanhap(zB) : sigap(zB);
            }
            c1a = fmaf(gA[1], c1a, gA[0] * gA[2]);
            c1b = fmaf(gB[1], c1b, gB[0] * gB[2]);
            float hA = gA[3] * tanhap(c1a);
            float hB = gB[3] * tanhap(c1b);

            ull svA = pack2(hA, hA * hA);
            ull svB = pack2(hB, hB * hB);
#pragma unroll
            for (int off = 16; off; off >>= 1) {
                fadd2(svA, __shfl_xor_sync(0xffffffffu, svA, off));
                fadd2(svB, __shfl_xor_sync(0xffffffffu, svB, off));
            }
            float2 sA = unpack2(svA), sB = unpack2(svB);
            float muA = sA.x * (1.0f / H);
            float muB = sB.x * (1.0f / H);
            rinvA = rsqrtf(fmaf(-muA, muA, sA.y * (1.0f / H)) + 1e-5f);
            rinvB = rsqrtf(fmaf(-muB, muB, sB.y * (1.0f / H)) + 1e-5f);
            mriA = -muA * rinvA;
            mriB = -muB * rinvB;
            h1s[nA][lane] = hA;
            h1s[nB][lane] = hB;
        }
        __syncthreads();
    }
}

// =====================================================================
// GCN stage (unchanged)
// =====================================================================
__global__ void dinv_init_kernel() {
    int i = blockIdx.x * blockDim.x + threadIdx.x;
    if (i < N_NODES) g_dinv[i] = 1.0f;
}
__global__ void deg_acc_kernel(const int* __restrict__ ei, const float* __restrict__ ew) {
    int e = blockIdx.x * blockDim.x + threadIdx.x;
    if (e < NE) atomicAdd(&g_dinv[ei[NE + e]], ew[e]);
}
__global__ void dinv_fin_kernel() {
    int i = blockIdx.x * blockDim.x + threadIdx.x;
    if (i < N_NODES) g_dinv[i] = rsqrtf(g_dinv[i]);
}

__global__ void gcn_pre_kernel(const float* __restrict__ inp, const float* __restrict__ Wg,
                               const float* __restrict__ bprev, int apply_elu)
{
    __shared__ float Ws[H * H];
    __shared__ float rows[8][H];
    int tid = threadIdx.x;
    int m = tid >> 5, u = tid & 31;
    int n = blockIdx.x * 8 + m;
    for (int i = tid; i < H * H; i += 256) Ws[i] = Wg[i];
    float v = inp[n * H + u];
    if (apply_elu) { v += bprev[u]; v = v > 0.f ? v : expm1f(v); }
    rows[m][u] = v;
    __syncthreads();
    float acc = 0.f;
#pragma unroll
    for (int k = 0; k < H; k++) acc = fmaf(rows[m][k], Ws[k * H + u], acc);
    float di = g_dinv[n];
    g_hW[n * H + u]  = acc;
    g_agg[n * H + u] = acc * di * di;
}

__global__ void gcn_scatter_kernel(const int* __restrict__ ei, const float* __restrict__ ew)
{
    int idx = blockIdx.x * blockDim.x + threadIdx.x;
    int e = idx >> 5, u = idx & 31;
    int s = ei[e];
    int d = ei[NE + e];
    float nrm = g_dinv[s] * ew[e] * g_dinv[d];
    atomicAdd(&g_agg[d * H + u], nrm * g_hW[s * H + u]);
}

__global__ void final_kernel(const float* __restrict__ bg2, const float* __restrict__ Wfc,
                             const float* __restrict__ bfc, float* __restrict__ out)
{
    int tid = threadIdx.x;
    int m = tid >> 5, u = tid & 31;
    int n = blockIdx.x * 8 + m;
    float g = g_agg[n * H + u] + bg2[u];
    g = g > 0.f ? g : expm1f(g);
    float s = g;
#pragma unroll
    for (int off = 16; off; off >>= 1) s += __shfl_xor_sync(0xffffffffu, s, off);
    float mean = s * (1.0f / H);
    float h2u = g_h2[n * H + u];
    float p0 = h2u * Wfc[u];
    float p1 = h2u * Wfc[33 + u];
#pragma unroll
    for (int off = 16; off; off >>= 1) {
        p0 += __shfl_xor_sync(0xffffffffu, p0, off);
        p1 += __shfl_xor_sync(0xffffffffu, p1, off);
    }
    if (u == 0) {
        float o0 = p0 + mean * Wfc[32]      + bfc[0];
        float o1 = p1 + mean * Wfc[33 + 32] + bfc[1];
        float mx = fmaxf(o0, o1);
        float lse = mx + logf(expf(o0 - mx) + expf(o1 - mx));
        out[n * 2 + 0] = o0 - lse;
        out[n * 2 + 1] = o1 - lse;
    }
}

// =====================================================================
extern "C" void kernel_launch(void* const* d_in, const int* in_sizes, int n_in,
                              void* d_out, int out_size)
{
    const float* x    = (const float*)d_in[0];
    const float* ew   = (const float*)d_in[1];
    const float* Wih1 = (const float*)d_in[2];
    const float* Whh1 = (const float*)d_in[3];
    const float* bih1 = (const float*)d_in[4];
    const float* bhh1 = (const float*)d_in[5];
    const float* lng  = (const float*)d_in[6];
    const float* lnb  = (const float*)d_in[7];
    const float* Wih2 = (const float*)d_in[8];
    const float* Whh2 = (const float*)d_in[9];
    const float* bih2 = (const float*)d_in[10];
    const float* bhh2 = (const float*)d_in[11];
    const float* Wg1  = (const float*)d_in[12];
    const float* bg1  = (const float*)d_in[13];
    const float* Wg2  = (const float*)d_in[14];
    const float* bg2  = (const float*)d_in[15];
    const float* Wfc  = (const float*)d_in[16];
    const float* bfc  = (const float*)d_in[17];
    const int*   eidx = (const int*)d_in[18];
    float* out = (float*)d_out;

    // keep lstm_kernel as launch #4 for the fixed-skip ncu capture
    dinv_init_kernel<<<N_NODES / 256, 256>>>();
    deg_acc_kernel<<<NE / 256, 256>>>(eidx, ew);
    dinv_fin_kernel<<<N_NODES / 256, 256>>>();

    lstm_kernel<<<N_NODES / NPB, 128>>>(x, Wih1, Whh1, bih1, bhh1, lng, lnb,
                                        Wih2, Whh2, bih2, bhh2);

    gcn_pre_kernel<<<N_NODES / 8, 256>>>(g_h2, Wg1, bg1, 0);
    gcn_scatter_kernel<<<(NE * 32) / 256, 256>>>(eidx, ew);

    gcn_pre_kernel<<<N_NODES / 8, 256>>>(g_agg, Wg2, bg1, 1);
    gcn_scatter_kernel<<<(NE * 32) / 256, 256>>>(eidx, ew);

    final_kernel<<<N_NODES / 8, 256>>>(bg2, Wfc, bfc, out);
}

// round 11
// speedup vs baseline: 1.1250x; 1.0996x over previous
#include <cuda_runtime.h>
#include <math.h>

#define N_NODES 8192
#define SEQ 256
#define H 32
#define G4 128
#define NPB 8
#define NE 262144

typedef unsigned long long ull;

__device__ float g_h2[N_NODES * H];
__device__ float g_hW[N_NODES * H];
__device__ float g_agg[N_NODES * H];
__device__ float g_dinv[N_NODES];

__device__ __forceinline__ void ffma2(ull& d, ull a, ull b) {
    asm("fma.rn.f32x2 %0, %1, %2, %0;" : "+l"(d) : "l"(a), "l"(b));
}
__device__ __forceinline__ void fadd2(ull& d, ull a) {
    asm("add.rn.f32x2 %0, %0, %1;" : "+l"(d) : "l"(a));
}
__device__ __forceinline__ ull pack2(float lo, float hi) {
    ull r; asm("mov.b64 %0, {%1, %2};" : "=l"(r) : "f"(lo), "f"(hi)); return r;
}
__device__ __forceinline__ float2 unpack2(ull v) {
    float2 r; asm("mov.b64 {%0, %1}, %2;" : "=f"(r.x), "=f"(r.y) : "l"(v)); return r;
}
__device__ __forceinline__ float tanhap(float x) {
    float r; asm("tanh.approx.f32 %0, %1;" : "=f"(r) : "f"(x)); return r;
}
__device__ __forceinline__ float sigap(float x) {
    return fmaf(0.5f, tanhap(0.5f * x), 0.5f);
}

// =====================================================================
// Fused 2-layer LSTM, LN folded into the LSTM2 input matvec so that
// BOTH matvecs in Phase1 read h1 (shared loads) + h2. No ys array.
// Thread j owns z-row j (full k). 8 nodes/block, 3 blocks/SM,
// 2 barriers/step (skewed schedule):
//   Phase1(t): z1(t) = act(Whh1*h1 + x*w + b)
//              z2(t-1) = act(rinv*(Wtil*h1) + mri*stil + q + Whh2*h2)
//   Phase2(t): cell1(t)+LN stats -> h1, rm ; cell2(t-1) -> h2
// =====================================================================
__global__ void __launch_bounds__(128, 3) lstm_kernel(
    const float* __restrict__ x,
    const float* __restrict__ Wih1, const float* __restrict__ Whh1,
    const float* __restrict__ bih1, const float* __restrict__ bhh1,
    const float* __restrict__ ln_g, const float* __restrict__ ln_b,
    const float* __restrict__ Wih2, const float* __restrict__ Whh2,
    const float* __restrict__ bih2, const float* __restrict__ bhh2)
{
    __shared__ __align__(16) float xs[NPB][SEQ];
    __shared__ __align__(16) float h1s[NPB][H];
    __shared__ __align__(16) float h2s[NPB][H];
    __shared__ __align__(16) float z1s[NPB][G4];
    __shared__ __align__(16) float z2s[NPB][G4];
    __shared__ float2 rm[NPB];                 // (rinv, -mu*rinv) per node

    const int tid  = threadIdx.x;
    const int j    = tid;
    const int base = blockIdx.x * NPB;

    // ---- per-row weights -> registers (packed pairs) ----
    ull w1p[H / 2], wt2p[H / 2], wh2p[H / 2];
    float stil_j = 0.f, q_j = 0.f;
    {
#pragma unroll
        for (int k2 = 0; k2 < H / 2; k2++) {
            int k = 2 * k2;
            float g0 = ln_g[k], g1 = ln_g[k + 1];
            float wa = Wih2[j * H + k], wb = Wih2[j * H + k + 1];
            w1p[k2]  = pack2(Whh1[j * H + k], Whh1[j * H + k + 1]);
            wt2p[k2] = pack2(wa * g0, wb * g1);
            wh2p[k2] = pack2(Whh2[j * H + k], Whh2[j * H + k + 1]);
            stil_j += wa * g0 + wb * g1;
            q_j    += wa * ln_b[k] + wb * ln_b[k + 1];
        }
        q_j += bih2[j] + bhh2[j];
    }
    const float b1j = bih1[j] + bhh1[j];
    const float wx1 = Wih1[j];
    const int   gate = j >> 5;                // uniform per warp
    const float mS = (gate == 2) ? 1.0f : 0.5f;
    const float mA = (gate == 2) ? 1.0f : 0.5f;
    const float mB = (gate == 2) ? 0.0f : 0.5f;

    const int mA0 = tid >> 5;
    const int mA1 = mA0 + 4;
    const int u   = tid & 31;
    float c1a = 0.f, c2a = 0.f, c1b = 0.f, c2b = 0.f;

    for (int idx = tid; idx < NPB * SEQ; idx += 128) {
        int m = idx >> 8, t = idx & 255;
        xs[m][t] = x[(base + m) * SEQ + t];
    }
    h1s[mA0][u] = 0.f; h1s[mA1][u] = 0.f;
    h2s[mA0][u] = 0.f; h2s[mA1][u] = 0.f;
    __syncthreads();

    for (int t = 0; t <= SEQ; t++) {
        const int tx = (t < SEQ) ? t : SEQ - 1;
        // ================= Phase1 =================
#pragma unroll
        for (int m = 0; m < NPB; m++) {
            ull a1 = pack2(fmaf(xs[m][tx], wx1, b1j), 0.f);
            ull a2 = 0ULL, a3 = 0ULL;
#pragma unroll
            for (int k4 = 0; k4 < H / 4; k4++) {
                ulonglong2 hv = *(const ulonglong2*)&h1s[m][k4 * 4];
                ffma2(a1, w1p[2 * k4],      hv.x);
                ffma2(a1, w1p[2 * k4 + 1],  hv.y);
                ffma2(a2, wt2p[2 * k4],     hv.x);
                ffma2(a2, wt2p[2 * k4 + 1], hv.y);
            }
#pragma unroll
            for (int k4 = 0; k4 < H / 4; k4++) {
                ulonglong2 hv = *(const ulonglong2*)&h2s[m][k4 * 4];
                ffma2(a3, wh2p[2 * k4],     hv.x);
                ffma2(a3, wh2p[2 * k4 + 1], hv.y);
            }
            float2 p1 = unpack2(a1);
            z1s[m][j] = fmaf(mA, tanhap(mS * (p1.x + p1.y)), mB);
            if (t) {
                float2 p2 = unpack2(a2);
                float2 p3 = unpack2(a3);
                float2 rmm = rm[m];
                float z2 = fmaf(rmm.x, p2.x + p2.y,
                                fmaf(rmm.y, stil_j, q_j) + p3.x + p3.y);
                z2s[m][j] = fmaf(mA, tanhap(mS * z2), mB);
            }
        }
        __syncthreads();

        // ================= Phase2 =================
        if (t) {   // cell2(t-1)
            float gia = z2s[mA0][u], gfa = z2s[mA0][H + u];
            float gga = z2s[mA0][2 * H + u], goa = z2s[mA0][3 * H + u];
            float gib = z2s[mA1][u], gfb = z2s[mA1][H + u];
            float ggb = z2s[mA1][2 * H + u], gob = z2s[mA1][3 * H + u];
            c2a = fmaf(gfa, c2a, gia * gga);
            c2b = fmaf(gfb, c2b, gib * ggb);
            float hA = goa * tanhap(c2a);
            float hB = gob * tanhap(c2b);
            if (t < SEQ) { h2s[mA0][u] = hA; h2s[mA1][u] = hB; }
            else {
                g_h2[(base + mA0) * H + u] = hA;
                g_h2[(base + mA1) * H + u] = hB;
            }
        }
        if (t < SEQ) {   // cell1(t) + LN stats
            float gia = z1s[mA0][u], gfa = z1s[mA0][H + u];
            float gga = z1s[mA0][2 * H + u], goa = z1s[mA0][3 * H + u];
            float gib = z1s[mA1][u], gfb = z1s[mA1][H + u];
            float ggb = z1s[mA1][2 * H + u], gob = z1s[mA1][3 * H + u];
            c1a = fmaf(gfa, c1a, gia * gga);
            c1b = fmaf(gfb, c1b, gib * ggb);
            float hA = goa * tanhap(c1a);
            float hB = gob * tanhap(c1b);

            ull svA = pack2(hA, hA * hA);
            ull svB = pack2(hB, hB * hB);
#pragma unroll
            for (int off = 16; off; off >>= 1) {
                fadd2(svA, __shfl_xor_sync(0xffffffffu, svA, off));
                fadd2(svB, __shfl_xor_sync(0xffffffffu, svB, off));
            }
            float2 sA = unpack2(svA), sB = unpack2(svB);
            float muA = sA.x * (1.0f / H);
            float muB = sB.x * (1.0f / H);
            float riA = rsqrtf(fmaf(-muA, muA, sA.y * (1.0f / H)) + 1e-5f);
            float riB = rsqrtf(fmaf(-muB, muB, sB.y * (1.0f / H)) + 1e-5f);
            h1s[mA0][u] = hA;
            h1s[mA1][u] = hB;
            if (u == 0) {
                rm[mA0] = make_float2(riA, -muA * riA);
                rm[mA1] = make_float2(riB, -muB * riB);
            }
        }
        __syncthreads();
    }
}

// =====================================================================
// GCN stage (unchanged)
// =====================================================================
__global__ void dinv_init_kernel() {
    int i = blockIdx.x * blockDim.x + threadIdx.x;
    if (i < N_NODES) g_dinv[i] = 1.0f;
}
__global__ void deg_acc_kernel(const int* __restrict__ ei, const float* __restrict__ ew) {
    int e = blockIdx.x * blockDim.x + threadIdx.x;
    if (e < NE) atomicAdd(&g_dinv[ei[NE + e]], ew[e]);
}
__global__ void dinv_fin_kernel() {
    int i = blockIdx.x * blockDim.x + threadIdx.x;
    if (i < N_NODES) g_dinv[i] = rsqrtf(g_dinv[i]);
}

__global__ void gcn_pre_kernel(const float* __restrict__ inp, const float* __restrict__ Wg,
                               const float* __restrict__ bprev, int apply_elu)
{
    __shared__ float Ws[H * H];
    __shared__ float rows[8][H];
    int tid = threadIdx.x;
    int m = tid >> 5, u = tid & 31;
    int n = blockIdx.x * 8 + m;
    for (int i = tid; i < H * H; i += 256) Ws[i] = Wg[i];
    float v = inp[n * H + u];
    if (apply_elu) { v += bprev[u]; v = v > 0.f ? v : expm1f(v); }
    rows[m][u] = v;
    __syncthreads();
    float acc = 0.f;
#pragma unroll
    for (int k = 0; k < H; k++) acc = fmaf(rows[m][k], Ws[k * H + u], acc);
    float di = g_dinv[n];
    g_hW[n * H + u]  = acc;
    g_agg[n * H + u] = acc * di * di;
}

__global__ void gcn_scatter_kernel(const int* __restrict__ ei, const float* __restrict__ ew)
{
    int idx = blockIdx.x * blockDim.x + threadIdx.x;
    int e = idx >> 5, u = idx & 31;
    int s = ei[e];
    int d = ei[NE + e];
    float nrm = g_dinv[s] * ew[e] * g_dinv[d];
    atomicAdd(&g_agg[d * H + u], nrm * g_hW[s * H + u]);
}

__global__ void final_kernel(const float* __restrict__ bg2, const float* __restrict__ Wfc,
                             const float* __restrict__ bfc, float* __restrict__ out)
{
    int tid = threadIdx.x;
    int m = tid >> 5, u = tid & 31;
    int n = blockIdx.x * 8 + m;
    float g = g_agg[n * H + u] + bg2[u];
    g = g > 0.f ? g : expm1f(g);
    float s = g;
#pragma unroll
    for (int off = 16; off; off >>= 1) s += __shfl_xor_sync(0xffffffffu, s, off);
    float mean = s * (1.0f / H);
    float h2u = g_h2[n * H + u];
    float p0 = h2u * Wfc[u];
    float p1 = h2u * Wfc[33 + u];
#pragma unroll
    for (int off = 16; off; off >>= 1) {
        p0 += __shfl_xor_sync(0xffffffffu, p0, off);
        p1 += __shfl_xor_sync(0xffffffffu, p1, off);
    }
    if (u == 0) {
        float o0 = p0 + mean * Wfc[32]      + bfc[0];
        float o1 = p1 + mean * Wfc[33 + 32] + bfc[1];
        float mx = fmaxf(o0, o1);
        float lse = mx + logf(expf(o0 - mx) + expf(o1 - mx));
        out[n * 2 + 0] = o0 - lse;
        out[n * 2 + 1] = o1 - lse;
    }
}

// =====================================================================
extern "C" void kernel_launch(void* const* d_in, const int* in_sizes, int n_in,
                              void* d_out, int out_size)
{
    const float* x    = (const float*)d_in[0];
    const float* ew   = (const float*)d_in[1];
    const float* Wih1 = (const float*)d_in[2];
    const float* Whh1 = (const float*)d_in[3];
    const float* bih1 = (const float*)d_in[4];
    const float* bhh1 = (const float*)d_in[5];
    const float* lng  = (const float*)d_in[6];
    const float* lnb  = (const float*)d_in[7];
    const float* Wih2 = (const float*)d_in[8];
    const float* Whh2 = (const float*)d_in[9];
    const float* bih2 = (const float*)d_in[10];
    const float* bhh2 = (const float*)d_in[11];
    const float* Wg1  = (const float*)d_in[12];
    const float* bg1  = (const float*)d_in[13];
    const float* Wg2  = (const float*)d_in[14];
    const float* bg2  = (const float*)d_in[15];
    const float* Wfc  = (const float*)d_in[16];
    const float* bfc  = (const float*)d_in[17];
    const int*   eidx = (const int*)d_in[18];
    float* out = (float*)d_out;

    // keep lstm_kernel as launch #4 for the fixed-skip ncu capture
    dinv_init_kernel<<<N_NODES / 256, 256>>>();
    deg_acc_kernel<<<NE / 256, 256>>>(eidx, ew);
    dinv_fin_kernel<<<N_NODES / 256, 256>>>();

    lstm_kernel<<<N_NODES / NPB, 128>>>(x, Wih1, Whh1, bih1, bhh1, lng, lnb,
                                        Wih2, Whh2, bih2, bhh2);

    gcn_pre_kernel<<<N_NODES / 8, 256>>>(g_h2, Wg1, bg1, 0);
    gcn_scatter_kernel<<<(NE * 32) / 256, 256>>>(eidx, ew);

    gcn_pre_kernel<<<N_NODES / 8, 256>>>(g_agg, Wg2, bg1, 1);
    gcn_scatter_kernel<<<(NE * 32) / 256, 256>>>(eidx, ew);

    final_kernel<<<N_NODES / 8, 256>>>(bg2, Wfc, bfc, out);
}